// round 10
// baseline (speedup 1.0000x reference)
#include <cuda_runtime.h>
#include <math.h>

#define NN 50000
#define EE 800000
#define DD 128
#define CSR_GRID 200

// ---------------- scratch (device globals; allocation-free rule) ----------------
__device__ int   g_deg[NN];
__device__ int   g_rowptr[NN + 1];
__device__ int   g_cursor[NN];
__device__ int   g_cols[EE];
__device__ float g_dis[NN];
__device__ int   g_bsum[256];
__device__ int   g_boff[256];
__device__ __align__(16) float g_h[NN * DD];
__device__ __align__(16) float g_agg[NN * DD];
__device__ __align__(16) float g_x[NN * DD];
__device__ float g_stats[3 * 2 * DD];   // per-layer: [l*256 + 0..127]=sum, [l*256+128..255]=sumsq
__device__ int   g_bar_count;
__device__ volatile int g_bar_phase;

// ---------------- grid barrier (sense-reversing, bounded spin) ----------------
__device__ __forceinline__ void grid_bar() {
    __syncthreads();
    if (threadIdx.x == 0) {
        int gen = g_bar_phase;
        __threadfence();
        if (atomicAdd(&g_bar_count, 1) == (int)gridDim.x - 1) {
            g_bar_count = 0;
            __threadfence();
            g_bar_phase = gen + 1;
        } else {
            // bounded spin: on logic bug we produce wrong answers, never a hang
            for (int t = 0; t < (1 << 22) && g_bar_phase == gen; ++t) { }
        }
    }
    __syncthreads();
}

// ---------------- fused CSR build: zero + degree + scan + apply + fill ----------------
__global__ __launch_bounds__(256) void csr_build_kernel(const int* __restrict__ src,
                                                        const int* __restrict__ dst,
                                                        int n, int e) {
    __shared__ int wsum[8];
    int tid = threadIdx.x;
    int lane = tid & 31, wid = tid >> 5;
    int gtid = blockIdx.x * 256 + tid;
    int gsz = gridDim.x * 256;
    int nb = (n + 255) / 256;

    // phase 1: zero degree + all per-layer stats
    for (int i = gtid; i < n; i += gsz) g_deg[i] = 0;
    for (int i = gtid; i < 3 * 2 * DD; i += gsz) g_stats[i] = 0.0f;
    grid_bar();

    // phase 2: degree histogram
    for (int i = gtid; i < e; i += gsz) atomicAdd(&g_deg[dst[i]], 1);
    grid_bar();

    // phase 3: per-chunk local exclusive scan (chunk b handled by block b)
    for (int b = blockIdx.x; b < nb; b += gridDim.x) {
        __syncthreads();
        int i = b * 256 + tid;
        int v = (i < n) ? g_deg[i] : 0;
        int incl = v;
        #pragma unroll
        for (int off = 1; off < 32; off <<= 1) {
            int t = __shfl_up_sync(0xffffffffu, incl, off);
            if (lane >= off) incl += t;
        }
        if (lane == 31) wsum[wid] = incl;
        __syncthreads();
        if (wid == 0 && lane < 8) {
            int w = wsum[lane];
            int s = w;
            #pragma unroll
            for (int off = 1; off < 8; off <<= 1) {
                int t = __shfl_up_sync(0xffu, s, off);
                if (lane >= off) s += t;
            }
            wsum[lane] = s - w;
        }
        __syncthreads();
        int excl = incl - v + wsum[wid];
        if (i < n) g_rowptr[i] = excl;          // local exclusive (offset applied later)
        if (tid == 255) g_bsum[b] = excl + v;   // chunk total
    }
    grid_bar();

    // phase 4: block 0 scans chunk totals (nb <= 256)
    if (blockIdx.x == 0) {
        int v = (tid < nb) ? g_bsum[tid] : 0;
        int incl = v;
        #pragma unroll
        for (int off = 1; off < 32; off <<= 1) {
            int t = __shfl_up_sync(0xffffffffu, incl, off);
            if (lane >= off) incl += t;
        }
        if (lane == 31) wsum[wid] = incl;
        __syncthreads();
        if (wid == 0 && lane < 8) {
            int w = wsum[lane];
            int s = w;
            #pragma unroll
            for (int off = 1; off < 8; off <<= 1) {
                int t = __shfl_up_sync(0xffu, s, off);
                if (lane >= off) s += t;
            }
            wsum[lane] = s - w;
        }
        __syncthreads();
        int excl = incl - v + wsum[wid];
        if (tid < nb) g_boff[tid] = excl;
        if (tid == nb - 1) g_rowptr[n] = excl + v;
    }
    grid_bar();

    // phase 5: apply chunk offsets; cursor + dis
    for (int b = blockIdx.x; b < nb; b += gridDim.x) {
        int i = b * 256 + tid;
        if (i < n) {
            int excl = g_rowptr[i] + g_boff[b];
            g_rowptr[i] = excl;
            g_cursor[i] = excl;
            g_dis[i] = rsqrtf((float)g_deg[i] + 1.0f);
        }
    }
    grid_bar();

    // phase 6: fill column lists
    for (int i = gtid; i < e; i += gsz) {
        int d = dst[i];
        int pos = atomicAdd(&g_cursor[d], 1);
        g_cols[pos] = src[i];
    }
}

// ---------------- GEMM: g_h = dis .* (X @ W)  (proven fp32 core) ----------------
// mode 0: X = Xext. mode 1: v = relu(bn_{prev}(agg)) (+ g_x if residual); g_x = v; X = v.
// BN scale/shift of the previous layer recomputed per block from g_stats[(layer-1)*256+..].
__global__ __launch_bounds__(256) void gemm_kernel(const float* __restrict__ Xext,
                                                   const float* __restrict__ W,
                                                   const float* __restrict__ gamma_prev,
                                                   const float* __restrict__ beta_prev,
                                                   int n, int mode, int residual,
                                                   int layer, float invn) {
    __shared__ __align__(16) float xs[64][32];
    __shared__ __align__(16) float ws[32][128];
    __shared__ float sscale[DD];
    __shared__ float sshift[DD];
    int tid = threadIdx.x;
    int tx = tid & 31, ty = tid >> 5;
    int m0 = blockIdx.x * 64;

    if (mode == 1 && tid < DD) {
        int base = (layer - 1) * 2 * DD;
        float s  = g_stats[base + tid];
        float sq = g_stats[base + DD + tid];
        float mean = s * invn;
        float var  = sq * invn - mean * mean;
        float istd = rsqrtf(var + 1e-5f);
        float sc = gamma_prev[tid] * istd;
        sscale[tid] = sc;
        sshift[tid] = beta_prev[tid] - mean * sc;
    }
    if (mode == 1) __syncthreads();

    float4 acc[8];
    #pragma unroll
    for (int j = 0; j < 8; j++) acc[j] = make_float4(0.f, 0.f, 0.f, 0.f);

    for (int kc = 0; kc < 128; kc += 32) {
        #pragma unroll
        for (int i = 0; i < 8; i++) {
            int lin = tid + 256 * i;
            int r = lin >> 5, c = lin & 31;
            int row = m0 + r;
            float v = 0.0f;
            if (row < n) {
                int idx = row * 128 + kc + c;
                if (mode == 0) {
                    v = Xext[idx];
                } else {
                    float a = g_agg[idx];
                    v = a * sscale[kc + c] + sshift[kc + c];
                    v = fmaxf(v, 0.0f);
                    if (residual) v += g_x[idx];
                    g_x[idx] = v;
                }
            }
            xs[r][c] = v;
        }
        #pragma unroll
        for (int i = 0; i < 4; i++) {
            int lin = tid + 256 * i;
            int r = lin >> 5, c4 = lin & 31;
            *(float4*)&ws[r][c4 * 4] = *(const float4*)&W[(kc + r) * 128 + c4 * 4];
        }
        __syncthreads();
        #pragma unroll
        for (int k = 0; k < 32; k++) {
            float4 wv = *(const float4*)&ws[k][tx * 4];
            #pragma unroll
            for (int j = 0; j < 8; j++) {
                float xv = xs[ty * 8 + j][k];
                acc[j].x += xv * wv.x;
                acc[j].y += xv * wv.y;
                acc[j].z += xv * wv.z;
                acc[j].w += xv * wv.w;
            }
        }
        __syncthreads();
    }
    #pragma unroll
    for (int j = 0; j < 8; j++) {
        int row = m0 + ty * 8 + j;
        if (row < n) {
            float dn = g_dis[row];
            acc[j].x *= dn; acc[j].y *= dn; acc[j].z *= dn; acc[j].w *= dn;
            *(float4*)&g_h[row * 128 + tx * 4] = acc[j];
        }
    }
}

// ---------------- Aggregation (warp/node) + per-layer BN stat partials ----------------
__global__ __launch_bounds__(256) void agg_kernel(const float* __restrict__ bias, int n,
                                                  int layer) {
    __shared__ float red[8][256];
    int tid = threadIdx.x;
    int lane = tid & 31, wid = tid >> 5;
    float4 bv = *(const float4*)&bias[lane * 4];

    float ls0 = 0.f, ls1 = 0.f, ls2 = 0.f, ls3 = 0.f;
    float lq0 = 0.f, lq1 = 0.f, lq2 = 0.f, lq3 = 0.f;

    for (int node = blockIdx.x * 8 + wid; node < n; node += gridDim.x * 8) {
        int beg = __ldg(&g_rowptr[node]);
        int end = __ldg(&g_rowptr[node + 1]);
        float ax = 0.f, ay = 0.f, az = 0.f, aw = 0.f;
        int j = beg;
        for (; j + 3 < end; j += 4) {
            int c0 = __ldg(&g_cols[j]);
            int c1 = __ldg(&g_cols[j + 1]);
            int c2 = __ldg(&g_cols[j + 2]);
            int c3 = __ldg(&g_cols[j + 3]);
            float4 h0 = *(const float4*)&g_h[c0 * 128 + lane * 4];
            float4 h1 = *(const float4*)&g_h[c1 * 128 + lane * 4];
            float4 h2 = *(const float4*)&g_h[c2 * 128 + lane * 4];
            float4 h3 = *(const float4*)&g_h[c3 * 128 + lane * 4];
            ax += h0.x + h1.x + h2.x + h3.x;
            ay += h0.y + h1.y + h2.y + h3.y;
            az += h0.z + h1.z + h2.z + h3.z;
            aw += h0.w + h1.w + h2.w + h3.w;
        }
        for (; j < end; j++) {
            int c0 = __ldg(&g_cols[j]);
            float4 h0 = *(const float4*)&g_h[c0 * 128 + lane * 4];
            ax += h0.x; ay += h0.y; az += h0.z; aw += h0.w;
        }
        float4 hs = *(const float4*)&g_h[node * 128 + lane * 4];
        float dn = __ldg(&g_dis[node]);
        ax = dn * (ax + hs.x) + bv.x;
        ay = dn * (ay + hs.y) + bv.y;
        az = dn * (az + hs.z) + bv.z;
        aw = dn * (aw + hs.w) + bv.w;
        *(float4*)&g_agg[node * 128 + lane * 4] = make_float4(ax, ay, az, aw);

        ls0 += ax; ls1 += ay; ls2 += az; ls3 += aw;
        lq0 += ax * ax; lq1 += ay * ay; lq2 += az * az; lq3 += aw * aw;
    }

    int sbase = layer * 2 * DD;
    red[wid][lane * 4 + 0] = ls0;
    red[wid][lane * 4 + 1] = ls1;
    red[wid][lane * 4 + 2] = ls2;
    red[wid][lane * 4 + 3] = ls3;
    __syncthreads();
    float tot = 0.f;
    #pragma unroll
    for (int w = 0; w < 8; w++) tot += red[w][tid];
    if (tid < 128) atomicAdd(&g_stats[sbase + tid], tot);
    __syncthreads();
    red[wid][lane * 4 + 0] = lq0;
    red[wid][lane * 4 + 1] = lq1;
    red[wid][lane * 4 + 2] = lq2;
    red[wid][lane * 4 + 3] = lq3;
    __syncthreads();
    tot = 0.f;
    #pragma unroll
    for (int w = 0; w < 8; w++) tot += red[w][tid];
    if (tid < 128) atomicAdd(&g_stats[sbase + DD + tid], tot);
}

// ---------------- Final elementwise: out = x2 + bn_2(agg2), no relu ----------------
__global__ __launch_bounds__(256) void elem_final_kernel(float* __restrict__ out,
                                                         const float* __restrict__ gamma,
                                                         const float* __restrict__ beta,
                                                         int n4, float invn) {
    __shared__ float sscale[DD];
    __shared__ float sshift[DD];
    int tid = threadIdx.x;
    if (tid < DD) {
        int base = 2 * 2 * DD;  // layer 2 stats
        float s  = g_stats[base + tid];
        float sq = g_stats[base + DD + tid];
        float mean = s * invn;
        float var  = sq * invn - mean * mean;
        float istd = rsqrtf(var + 1e-5f);
        float sc = gamma[tid] * istd;
        sscale[tid] = sc;
        sshift[tid] = beta[tid] - mean * sc;
    }
    __syncthreads();

    int idx = blockIdx.x * blockDim.x + tid;
    if (idx >= n4) return;
    int c4 = idx & 31;
    float4 sc = ((const float4*)sscale)[c4];
    float4 sh = ((const float4*)sshift)[c4];
    float4 a  = ((const float4*)g_agg)[idx];
    float4 r  = ((const float4*)g_x)[idx];
    float4 y;
    y.x = a.x * sc.x + sh.x + r.x;
    y.y = a.y * sc.y + sh.y + r.y;
    y.z = a.z * sc.z + sh.z + r.z;
    y.w = a.w * sc.w + sh.w + r.w;
    ((float4*)out)[idx] = y;
}

// ---------------- launch ----------------
extern "C" void kernel_launch(void* const* d_in, const int* in_sizes, int n_in,
                              void* d_out, int out_size) {
    const float* x      = (const float*)d_in[0];
    const int*   ei     = (const int*)d_in[1];
    const float* Ws     = (const float*)d_in[2];
    const float* bs     = (const float*)d_in[3];
    const float* gammas = (const float*)d_in[4];
    const float* betas  = (const float*)d_in[5];

    int n = in_sizes[0] / DD;   // 50000
    int e = in_sizes[1] / 2;    // 800000
    const int* src = ei;
    const int* dst = ei + e;

    csr_build_kernel<<<CSR_GRID, 256>>>(src, dst, n, e);

    float invn = 1.0f / (float)n;
    int n4 = n * (DD / 4);
    int gemm_grid = (n + 63) / 64;
    int agg_grid = 1184;

    for (int l = 0; l < 3; l++) {
        int mode = (l > 0) ? 1 : 0;
        int residual = (l > 1) ? 1 : 0;
        const float* gprev = gammas + (l > 0 ? (l - 1) : 0) * DD;
        const float* bprev = betas + (l > 0 ? (l - 1) : 0) * DD;
        gemm_kernel<<<gemm_grid, 256>>>(x, Ws + l * DD * DD, gprev, bprev,
                                        n, mode, residual, l, invn);
        agg_kernel<<<agg_grid, 256>>>(bs + l * DD, n, l);
    }
    elem_final_kernel<<<(n4 + 255) / 256, 256>>>((float*)d_out, gammas + 2 * DD,
                                                 betas + 2 * DD, n4, invn);
}

// round 11
// speedup vs baseline: 1.1166x; 1.1166x over previous
#include <cuda_runtime.h>
#include <math.h>

#define NN 50000
#define EE 800000
#define DD 128
#define CSR_GRID 200

// ---------------- scratch (device globals; allocation-free rule) ----------------
__device__ int   g_deg[NN];
__device__ int   g_rowptr[NN + 1];
__device__ int   g_cursor[NN];
__device__ int   g_cols[EE];
__device__ float g_dis[NN];
__device__ int   g_bsum[256];
__device__ int   g_boff[256];
__device__ __align__(16) float g_h[NN * DD];
__device__ __align__(16) float g_agg[NN * DD];
__device__ __align__(16) float g_x[NN * DD];
__device__ float g_stats[3 * 2 * DD];   // per-layer: sum / sumsq
__device__ int   g_bar_count;
__device__ volatile int g_bar_phase;

// ---------------- grid barrier (sense-reversing, bounded spin) ----------------
__device__ __forceinline__ void grid_bar() {
    __syncthreads();
    if (threadIdx.x == 0) {
        int gen = g_bar_phase;
        __threadfence();
        if (atomicAdd(&g_bar_count, 1) == (int)gridDim.x - 1) {
            g_bar_count = 0;
            __threadfence();
            g_bar_phase = gen + 1;
        } else {
            for (int t = 0; t < (1 << 22) && g_bar_phase == gen; ++t) { }
        }
    }
    __syncthreads();
}

// ---------------- fused CSR build: zero + degree + scan + apply + fill ----------------
__global__ __launch_bounds__(256) void csr_build_kernel(const int* __restrict__ src,
                                                        const int* __restrict__ dst,
                                                        int n, int e) {
    __shared__ int wsum[8];
    int tid = threadIdx.x;
    int lane = tid & 31, wid = tid >> 5;
    int gtid = blockIdx.x * 256 + tid;
    int gsz = gridDim.x * 256;
    int nb = (n + 255) / 256;

    for (int i = gtid; i < n; i += gsz) g_deg[i] = 0;
    for (int i = gtid; i < 3 * 2 * DD; i += gsz) g_stats[i] = 0.0f;
    grid_bar();

    for (int i = gtid; i < e; i += gsz) atomicAdd(&g_deg[dst[i]], 1);
    grid_bar();

    for (int b = blockIdx.x; b < nb; b += gridDim.x) {
        __syncthreads();
        int i = b * 256 + tid;
        int v = (i < n) ? g_deg[i] : 0;
        int incl = v;
        #pragma unroll
        for (int off = 1; off < 32; off <<= 1) {
            int t = __shfl_up_sync(0xffffffffu, incl, off);
            if (lane >= off) incl += t;
        }
        if (lane == 31) wsum[wid] = incl;
        __syncthreads();
        if (wid == 0 && lane < 8) {
            int w = wsum[lane];
            int s = w;
            #pragma unroll
            for (int off = 1; off < 8; off <<= 1) {
                int t = __shfl_up_sync(0xffu, s, off);
                if (lane >= off) s += t;
            }
            wsum[lane] = s - w;
        }
        __syncthreads();
        int excl = incl - v + wsum[wid];
        if (i < n) g_rowptr[i] = excl;
        if (tid == 255) g_bsum[b] = excl + v;
    }
    grid_bar();

    if (blockIdx.x == 0) {
        int v = (tid < nb) ? g_bsum[tid] : 0;
        int incl = v;
        #pragma unroll
        for (int off = 1; off < 32; off <<= 1) {
            int t = __shfl_up_sync(0xffffffffu, incl, off);
            if (lane >= off) incl += t;
        }
        if (lane == 31) wsum[wid] = incl;
        __syncthreads();
        if (wid == 0 && lane < 8) {
            int w = wsum[lane];
            int s = w;
            #pragma unroll
            for (int off = 1; off < 8; off <<= 1) {
                int t = __shfl_up_sync(0xffu, s, off);
                if (lane >= off) s += t;
            }
            wsum[lane] = s - w;
        }
        __syncthreads();
        int excl = incl - v + wsum[wid];
        if (tid < nb) g_boff[tid] = excl;
        if (tid == nb - 1) g_rowptr[n] = excl + v;
    }
    grid_bar();

    for (int b = blockIdx.x; b < nb; b += gridDim.x) {
        int i = b * 256 + tid;
        if (i < n) {
            int excl = g_rowptr[i] + g_boff[b];
            g_rowptr[i] = excl;
            g_cursor[i] = excl;
            g_dis[i] = rsqrtf((float)g_deg[i] + 1.0f);
        }
    }
    grid_bar();

    for (int i = gtid; i < e; i += gsz) {
        int d = dst[i];
        int pos = atomicAdd(&g_cursor[d], 1);
        g_cols[pos] = src[i];
    }
}

// ---------------- GEMM: g_h = dis .* (X @ W), 8x8 micro-tile ----------------
// block 128 threads: tx = tid&15 (8 cols each -> 128), ty = tid>>4 (8 rows each -> 64).
// M-tile 64, N-tile 128, K chunked by 32. smem 24KB -> 4+ blocks/SM.
// mode 0: X = Xext. mode 1: v = relu(bn_prev(agg)) (+ g_x if residual); g_x = v; X = v.
__global__ __launch_bounds__(128) void gemm_kernel(const float* __restrict__ Xext,
                                                   const float* __restrict__ W,
                                                   const float* __restrict__ gamma_prev,
                                                   const float* __restrict__ beta_prev,
                                                   int n, int mode, int residual,
                                                   int layer, float invn) {
    __shared__ __align__(16) float xs[64][32];
    __shared__ __align__(16) float ws[32][128];
    __shared__ float sscale[DD];
    __shared__ float sshift[DD];
    int tid = threadIdx.x;
    int tx = tid & 15, ty = tid >> 4;
    int m0 = blockIdx.x * 64;

    if (mode == 1) {
        if (tid < DD) {
            int base = (layer - 1) * 2 * DD;
            float s  = g_stats[base + tid];
            float sq = g_stats[base + DD + tid];
            float mean = s * invn;
            float var  = sq * invn - mean * mean;
            float istd = rsqrtf(var + 1e-5f);
            float sc = gamma_prev[tid] * istd;
            sscale[tid] = sc;
            sshift[tid] = beta_prev[tid] - mean * sc;
        }
        __syncthreads();
    }

    float4 acc[8][2];
    #pragma unroll
    for (int j = 0; j < 8; j++) {
        acc[j][0] = make_float4(0.f, 0.f, 0.f, 0.f);
        acc[j][1] = make_float4(0.f, 0.f, 0.f, 0.f);
    }

    for (int kc = 0; kc < 128; kc += 32) {
        // X tile (64 rows x 32 k), float4 per thread x4, sequential STS (conflict-free)
        #pragma unroll
        for (int i = 0; i < 4; i++) {
            int f = tid + 128 * i;          // float4 index in 64x8 grid
            int r = f >> 3, k4 = f & 7;
            int row = m0 + r;
            float4 v = make_float4(0.f, 0.f, 0.f, 0.f);
            if (row < n) {
                int idx = row * 128 + kc + k4 * 4;
                if (mode == 0) {
                    v = *(const float4*)&Xext[idx];
                } else {
                    float4 a = *(const float4*)&g_agg[idx];
                    int c = kc + k4 * 4;
                    v.x = fmaxf(a.x * sscale[c + 0] + sshift[c + 0], 0.f);
                    v.y = fmaxf(a.y * sscale[c + 1] + sshift[c + 1], 0.f);
                    v.z = fmaxf(a.z * sscale[c + 2] + sshift[c + 2], 0.f);
                    v.w = fmaxf(a.w * sscale[c + 3] + sshift[c + 3], 0.f);
                    if (residual) {
                        float4 rr = *(const float4*)&g_x[idx];
                        v.x += rr.x; v.y += rr.y; v.z += rr.z; v.w += rr.w;
                    }
                    *(float4*)&g_x[idx] = v;
                }
            }
            *(float4*)&xs[r][k4 * 4] = v;
        }
        // W tile (32 k x 128 cols), coalesced float4
        #pragma unroll
        for (int i = 0; i < 8; i++) {
            int f = tid + 128 * i;          // float4 index in 32x32 grid
            int r = f >> 5, c4 = f & 31;
            *(float4*)&ws[r][c4 * 4] = *(const float4*)&W[(kc + r) * 128 + c4 * 4];
        }
        __syncthreads();

        #pragma unroll
        for (int k = 0; k < 32; k++) {
            float4 wA = *(const float4*)&ws[k][tx * 8];
            float4 wB = *(const float4*)&ws[k][tx * 8 + 4];
            #pragma unroll
            for (int j = 0; j < 8; j++) {
                float xv = xs[ty * 8 + j][k];
                acc[j][0].x += xv * wA.x;
                acc[j][0].y += xv * wA.y;
                acc[j][0].z += xv * wA.z;
                acc[j][0].w += xv * wA.w;
                acc[j][1].x += xv * wB.x;
                acc[j][1].y += xv * wB.y;
                acc[j][1].z += xv * wB.z;
                acc[j][1].w += xv * wB.w;
            }
        }
        __syncthreads();
    }

    #pragma unroll
    for (int j = 0; j < 8; j++) {
        int row = m0 + ty * 8 + j;
        if (row < n) {
            float dn = g_dis[row];
            float4 a0 = acc[j][0], a1 = acc[j][1];
            a0.x *= dn; a0.y *= dn; a0.z *= dn; a0.w *= dn;
            a1.x *= dn; a1.y *= dn; a1.z *= dn; a1.w *= dn;
            *(float4*)&g_h[row * 128 + tx * 8]     = a0;
            *(float4*)&g_h[row * 128 + tx * 8 + 4] = a1;
        }
    }
}

// ---------------- Aggregation (warp/node) + per-layer BN stat partials ----------------
__global__ __launch_bounds__(256) void agg_kernel(const float* __restrict__ bias, int n,
                                                  int layer) {
    __shared__ float red[8][256];
    int tid = threadIdx.x;
    int lane = tid & 31, wid = tid >> 5;
    float4 bv = *(const float4*)&bias[lane * 4];

    float ls0 = 0.f, ls1 = 0.f, ls2 = 0.f, ls3 = 0.f;
    float lq0 = 0.f, lq1 = 0.f, lq2 = 0.f, lq3 = 0.f;

    for (int node = blockIdx.x * 8 + wid; node < n; node += gridDim.x * 8) {
        int beg = __ldg(&g_rowptr[node]);
        int end = __ldg(&g_rowptr[node + 1]);
        float ax = 0.f, ay = 0.f, az = 0.f, aw = 0.f;
        int j = beg;
        for (; j + 3 < end; j += 4) {
            int c0 = __ldg(&g_cols[j]);
            int c1 = __ldg(&g_cols[j + 1]);
            int c2 = __ldg(&g_cols[j + 2]);
            int c3 = __ldg(&g_cols[j + 3]);
            float4 h0 = *(const float4*)&g_h[c0 * 128 + lane * 4];
            float4 h1 = *(const float4*)&g_h[c1 * 128 + lane * 4];
            float4 h2 = *(const float4*)&g_h[c2 * 128 + lane * 4];
            float4 h3 = *(const float4*)&g_h[c3 * 128 + lane * 4];
            ax += h0.x + h1.x + h2.x + h3.x;
            ay += h0.y + h1.y + h2.y + h3.y;
            az += h0.z + h1.z + h2.z + h3.z;
            aw += h0.w + h1.w + h2.w + h3.w;
        }
        for (; j < end; j++) {
            int c0 = __ldg(&g_cols[j]);
            float4 h0 = *(const float4*)&g_h[c0 * 128 + lane * 4];
            ax += h0.x; ay += h0.y; az += h0.z; aw += h0.w;
        }
        float4 hs = *(const float4*)&g_h[node * 128 + lane * 4];
        float dn = __ldg(&g_dis[node]);
        ax = dn * (ax + hs.x) + bv.x;
        ay = dn * (ay + hs.y) + bv.y;
        az = dn * (az + hs.z) + bv.z;
        aw = dn * (aw + hs.w) + bv.w;
        *(float4*)&g_agg[node * 128 + lane * 4] = make_float4(ax, ay, az, aw);

        ls0 += ax; ls1 += ay; ls2 += az; ls3 += aw;
        lq0 += ax * ax; lq1 += ay * ay; lq2 += az * az; lq3 += aw * aw;
    }

    int sbase = layer * 2 * DD;
    red[wid][lane * 4 + 0] = ls0;
    red[wid][lane * 4 + 1] = ls1;
    red[wid][lane * 4 + 2] = ls2;
    red[wid][lane * 4 + 3] = ls3;
    __syncthreads();
    float tot = 0.f;
    #pragma unroll
    for (int w = 0; w < 8; w++) tot += red[w][tid];
    if (tid < 128) atomicAdd(&g_stats[sbase + tid], tot);
    __syncthreads();
    red[wid][lane * 4 + 0] = lq0;
    red[wid][lane * 4 + 1] = lq1;
    red[wid][lane * 4 + 2] = lq2;
    red[wid][lane * 4 + 3] = lq3;
    __syncthreads();
    tot = 0.f;
    #pragma unroll
    for (int w = 0; w < 8; w++) tot += red[w][tid];
    if (tid < 128) atomicAdd(&g_stats[sbase + DD + tid], tot);
}

// ---------------- Final elementwise: out = x2 + bn_2(agg2), no relu ----------------
__global__ __launch_bounds__(256) void elem_final_kernel(float* __restrict__ out,
                                                         const float* __restrict__ gamma,
                                                         const float* __restrict__ beta,
                                                         int n4, float invn) {
    __shared__ float sscale[DD];
    __shared__ float sshift[DD];
    int tid = threadIdx.x;
    if (tid < DD) {
        int base = 2 * 2 * DD;
        float s  = g_stats[base + tid];
        float sq = g_stats[base + DD + tid];
        float mean = s * invn;
        float var  = sq * invn - mean * mean;
        float istd = rsqrtf(var + 1e-5f);
        float sc = gamma[tid] * istd;
        sscale[tid] = sc;
        sshift[tid] = beta[tid] - mean * sc;
    }
    __syncthreads();

    int idx = blockIdx.x * blockDim.x + tid;
    if (idx >= n4) return;
    int c4 = idx & 31;
    float4 sc = ((const float4*)sscale)[c4];
    float4 sh = ((const float4*)sshift)[c4];
    float4 a  = ((const float4*)g_agg)[idx];
    float4 r  = ((const float4*)g_x)[idx];
    float4 y;
    y.x = a.x * sc.x + sh.x + r.x;
    y.y = a.y * sc.y + sh.y + r.y;
    y.z = a.z * sc.z + sh.z + r.z;
    y.w = a.w * sc.w + sh.w + r.w;
    ((float4*)out)[idx] = y;
}

// ---------------- launch ----------------
extern "C" void kernel_launch(void* const* d_in, const int* in_sizes, int n_in,
                              void* d_out, int out_size) {
    const float* x      = (const float*)d_in[0];
    const int*   ei     = (const int*)d_in[1];
    const float* Ws     = (const float*)d_in[2];
    const float* bs     = (const float*)d_in[3];
    const float* gammas = (const float*)d_in[4];
    const float* betas  = (const float*)d_in[5];

    int n = in_sizes[0] / DD;   // 50000
    int e = in_sizes[1] / 2;    // 800000
    const int* src = ei;
    const int* dst = ei + e;

    csr_build_kernel<<<CSR_GRID, 256>>>(src, dst, n, e);

    float invn = 1.0f / (float)n;
    int n4 = n * (DD / 4);
    int gemm_grid = (n + 63) / 64;
    int agg_grid = 1184;

    for (int l = 0; l < 3; l++) {
        int mode = (l > 0) ? 1 : 0;
        int residual = (l > 1) ? 1 : 0;
        const float* gprev = gammas + (l > 0 ? (l - 1) : 0) * DD;
        const float* bprev = betas + (l > 0 ? (l - 1) : 0) * DD;
        gemm_kernel<<<gemm_grid, 128>>>(x, Ws + l * DD * DD, gprev, bprev,
                                        n, mode, residual, l, invn);
        agg_kernel<<<agg_grid, 256>>>(bs + l * DD, n, l);
    }
    elem_final_kernel<<<(n4 + 255) / 256, 256>>>((float*)d_out, gammas + 2 * DD,
                                                 betas + 2 * DD, n4, invn);
}

// round 14
// speedup vs baseline: 1.1657x; 1.0440x over previous
#include <cuda_runtime.h>
#include <math.h>

#define NN 50000
#define EE 800000
#define DD 128
#define CSR_GRID 200

// ---------------- scratch (device globals; allocation-free rule) ----------------
__device__ int   g_deg[NN];
__device__ int   g_rowptr[NN + 1];
__device__ int   g_cursor[NN];
__device__ int   g_cols[EE];
__device__ float g_dis[NN];
__device__ int   g_bsum[256];
__device__ int   g_boff[256];
__device__ __align__(16) float g_h[NN * DD];
__device__ __align__(16) float g_agg[NN * DD];
__device__ __align__(16) float g_x[NN * DD];
__device__ float g_stats[3 * 2 * DD];   // per-layer: sum / sumsq
__device__ int   g_bar_count;
__device__ volatile int g_bar_phase;

// ---------------- grid barrier (sense-reversing, bounded spin) ----------------
__device__ __forceinline__ void grid_bar() {
    __syncthreads();
    if (threadIdx.x == 0) {
        int gen = g_bar_phase;
        __threadfence();
        if (atomicAdd(&g_bar_count, 1) == (int)gridDim.x - 1) {
            g_bar_count = 0;
            __threadfence();
            g_bar_phase = gen + 1;
        } else {
            for (int t = 0; t < (1 << 22) && g_bar_phase == gen; ++t) { }
        }
    }
    __syncthreads();
}

// ---------------- fused CSR build: zero + degree + scan + apply + fill ----------------
__global__ __launch_bounds__(256) void csr_build_kernel(const int* __restrict__ src,
                                                        const int* __restrict__ dst,
                                                        int n, int e) {
    __shared__ int wsum[8];
    int tid = threadIdx.x;
    int lane = tid & 31, wid = tid >> 5;
    int gtid = blockIdx.x * 256 + tid;
    int gsz = gridDim.x * 256;
    int nb = (n + 255) / 256;

    for (int i = gtid; i < n; i += gsz) g_deg[i] = 0;
    for (int i = gtid; i < 3 * 2 * DD; i += gsz) g_stats[i] = 0.0f;
    grid_bar();

    for (int i = gtid; i < e; i += gsz) atomicAdd(&g_deg[dst[i]], 1);
    grid_bar();

    for (int b = blockIdx.x; b < nb; b += gridDim.x) {
        __syncthreads();
        int i = b * 256 + tid;
        int v = (i < n) ? g_deg[i] : 0;
        int incl = v;
        #pragma unroll
        for (int off = 1; off < 32; off <<= 1) {
            int t = __shfl_up_sync(0xffffffffu, incl, off);
            if (lane >= off) incl += t;
        }
        if (lane == 31) wsum[wid] = incl;
        __syncthreads();
        if (wid == 0 && lane < 8) {
            int w = wsum[lane];
            int s = w;
            #pragma unroll
            for (int off = 1; off < 8; off <<= 1) {
                int t = __shfl_up_sync(0xffu, s, off);
                if (lane >= off) s += t;
            }
            wsum[lane] = s - w;
        }
        __syncthreads();
        int excl = incl - v + wsum[wid];
        if (i < n) g_rowptr[i] = excl;
        if (tid == 255) g_bsum[b] = excl + v;
    }
    grid_bar();

    if (blockIdx.x == 0) {
        int v = (tid < nb) ? g_bsum[tid] : 0;
        int incl = v;
        #pragma unroll
        for (int off = 1; off < 32; off <<= 1) {
            int t = __shfl_up_sync(0xffffffffu, incl, off);
            if (lane >= off) incl += t;
        }
        if (lane == 31) wsum[wid] = incl;
        __syncthreads();
        if (wid == 0 && lane < 8) {
            int w = wsum[lane];
            int s = w;
            #pragma unroll
            for (int off = 1; off < 8; off <<= 1) {
                int t = __shfl_up_sync(0xffu, s, off);
                if (lane >= off) s += t;
            }
            wsum[lane] = s - w;
        }
        __syncthreads();
        int excl = incl - v + wsum[wid];
        if (tid < nb) g_boff[tid] = excl;
        if (tid == nb - 1) g_rowptr[n] = excl + v;
    }
    grid_bar();

    for (int b = blockIdx.x; b < nb; b += gridDim.x) {
        int i = b * 256 + tid;
        if (i < n) {
            int excl = g_rowptr[i] + g_boff[b];
            g_rowptr[i] = excl;
            g_cursor[i] = excl;
            g_dis[i] = rsqrtf((float)g_deg[i] + 1.0f);
        }
    }
    grid_bar();

    for (int i = gtid; i < e; i += gsz) {
        int d = dst[i];
        int pos = atomicAdd(&g_cursor[d], 1);
        g_cols[pos] = src[i];
    }
}

// ---------------- GEMM: g_h = dis .* (X @ W), 8x8 micro-tile, conflict-free smem ----------------
// block 128 threads: tx = tid&15 (cols tx*4 and 64+tx*4), ty = tid>>4 (rows ty*8..+7).
// M-tile 64, N-tile 128, K chunked by 32. X tile stored TRANSPOSED xs[k][row] (pad 68).
// mode 0: X = Xext. mode 1: v = relu(bn_prev(agg)) (+ g_x if residual); g_x = v; X = v.
__global__ __launch_bounds__(128) void gemm_kernel(const float* __restrict__ Xext,
                                                   const float* __restrict__ W,
                                                   const float* __restrict__ gamma_prev,
                                                   const float* __restrict__ beta_prev,
                                                   int n, int mode, int residual,
                                                   int layer, float invn) {
    __shared__ __align__(16) float xs[32][68];   // [k][row], padded row stride
    __shared__ __align__(16) float ws[32][128];
    __shared__ float sscale[DD];
    __shared__ float sshift[DD];
    int tid = threadIdx.x;
    int tx = tid & 15, ty = tid >> 4;
    int m0 = blockIdx.x * 64;

    if (mode == 1) {
        if (tid < DD) {
            int base = (layer - 1) * 2 * DD;
            float s  = g_stats[base + tid];
            float sq = g_stats[base + DD + tid];
            float mean = s * invn;
            float var  = sq * invn - mean * mean;
            float istd = rsqrtf(var + 1e-5f);
            float sc = gamma_prev[tid] * istd;
            sscale[tid] = sc;
            sshift[tid] = beta_prev[tid] - mean * sc;
        }
        __syncthreads();
    }

    float4 acc[8][2];
    #pragma unroll
    for (int j = 0; j < 8; j++) {
        acc[j][0] = make_float4(0.f, 0.f, 0.f, 0.f);
        acc[j][1] = make_float4(0.f, 0.f, 0.f, 0.f);
    }

    for (int kc = 0; kc < 128; kc += 32) {
        // X tile (64 rows x 32 k), loaded row-major float4, stored transposed
        #pragma unroll
        for (int i = 0; i < 4; i++) {
            int f = tid + 128 * i;          // float4 index in 64x8 grid
            int r = f >> 3, k4 = f & 7;
            int row = m0 + r;
            float4 v = make_float4(0.f, 0.f, 0.f, 0.f);
            if (row < n) {
                int idx = row * 128 + kc + k4 * 4;
                if (mode == 0) {
                    v = *(const float4*)&Xext[idx];
                } else {
                    float4 a = *(const float4*)&g_agg[idx];
                    int c = kc + k4 * 4;
                    v.x = fmaxf(a.x * sscale[c + 0] + sshift[c + 0], 0.f);
                    v.y = fmaxf(a.y * sscale[c + 1] + sshift[c + 1], 0.f);
                    v.z = fmaxf(a.z * sscale[c + 2] + sshift[c + 2], 0.f);
                    v.w = fmaxf(a.w * sscale[c + 3] + sshift[c + 3], 0.f);
                    if (residual) {
                        float4 rr = *(const float4*)&g_x[idx];
                        v.x += rr.x; v.y += rr.y; v.z += rr.z; v.w += rr.w;
                    }
                    *(float4*)&g_x[idx] = v;
                }
            }
            xs[k4 * 4 + 0][r] = v.x;
            xs[k4 * 4 + 1][r] = v.y;
            xs[k4 * 4 + 2][r] = v.z;
            xs[k4 * 4 + 3][r] = v.w;
        }
        // W tile (32 k x 128 cols), coalesced float4
        #pragma unroll
        for (int i = 0; i < 8; i++) {
            int f = tid + 128 * i;          // float4 index in 32x32 grid
            int r = f >> 5, c4 = f & 31;
            *(float4*)&ws[r][c4 * 4] = *(const float4*)&W[(kc + r) * 128 + c4 * 4];
        }
        __syncthreads();

        #pragma unroll
        for (int k = 0; k < 32; k++) {
            float4 xA = *(const float4*)&xs[k][ty * 8];       // rows ty*8..+3
            float4 xB = *(const float4*)&xs[k][ty * 8 + 4];   // rows ty*8+4..+7
            float4 wA = *(const float4*)&ws[k][tx * 4];       // cols tx*4..+3
            float4 wB = *(const float4*)&ws[k][64 + tx * 4];  // cols 64+tx*4..+3
            #pragma unroll
            for (int j = 0; j < 4; j++) {
                float xv = (j == 0) ? xA.x : (j == 1) ? xA.y : (j == 2) ? xA.z : xA.w;
                acc[j][0].x += xv * wA.x;
                acc[j][0].y += xv * wA.y;
                acc[j][0].z += xv * wA.z;
                acc[j][0].w += xv * wA.w;
                acc[j][1].x += xv * wB.x;
                acc[j][1].y += xv * wB.y;
                acc[j][1].z += xv * wB.z;
                acc[j][1].w += xv * wB.w;
            }
            #pragma unroll
            for (int j = 0; j < 4; j++) {
                float xv = (j == 0) ? xB.x : (j == 1) ? xB.y : (j == 2) ? xB.z : xB.w;
                acc[4 + j][0].x += xv * wA.x;
                acc[4 + j][0].y += xv * wA.y;
                acc[4 + j][0].z += xv * wA.z;
                acc[4 + j][0].w += xv * wA.w;
                acc[4 + j][1].x += xv * wB.x;
                acc[4 + j][1].y += xv * wB.y;
                acc[4 + j][1].z += xv * wB.z;
                acc[4 + j][1].w += xv * wB.w;
            }
        }
        __syncthreads();
    }

    #pragma unroll
    for (int j = 0; j < 8; j++) {
        int row = m0 + ty * 8 + j;
        if (row < n) {
            float dn = g_dis[row];
            float4 a0 = acc[j][0], a1 = acc[j][1];
            a0.x *= dn; a0.y *= dn; a0.z *= dn; a0.w *= dn;
            a1.x *= dn; a1.y *= dn; a1.z *= dn; a1.w *= dn;
            *(float4*)&g_h[row * 128 + tx * 4]      = a0;
            *(float4*)&g_h[row * 128 + 64 + tx * 4] = a1;
        }
    }
}

// ---------------- Aggregation (warp/node) + per-layer BN stat partials ----------------
__global__ __launch_bounds__(256) void agg_kernel(const float* __restrict__ bias, int n,
                                                  int layer) {
    __shared__ float red[8][256];
    int tid = threadIdx.x;
    int lane = tid & 31, wid = tid >> 5;
    float4 bv = *(const float4*)&bias[lane * 4];

    float ls0 = 0.f, ls1 = 0.f, ls2 = 0.f, ls3 = 0.f;
    float lq0 = 0.f, lq1 = 0.f, lq2 = 0.f, lq3 = 0.f;

    for (int node = blockIdx.x * 8 + wid; node < n; node += gridDim.x * 8) {
        int beg = __ldg(&g_rowptr[node]);
        int end = __ldg(&g_rowptr[node + 1]);
        float ax = 0.f, ay = 0.f, az = 0.f, aw = 0.f;
        int j = beg;
        for (; j + 3 < end; j += 4) {
            int c0 = __ldg(&g_cols[j]);
            int c1 = __ldg(&g_cols[j + 1]);
            int c2 = __ldg(&g_cols[j + 2]);
            int c3 = __ldg(&g_cols[j + 3]);
            float4 h0 = *(const float4*)&g_h[c0 * 128 + lane * 4];
            float4 h1 = *(const float4*)&g_h[c1 * 128 + lane * 4];
            float4 h2 = *(const float4*)&g_h[c2 * 128 + lane * 4];
            float4 h3 = *(const float4*)&g_h[c3 * 128 + lane * 4];
            ax += h0.x + h1.x + h2.x + h3.x;
            ay += h0.y + h1.y + h2.y + h3.y;
            az += h0.z + h1.z + h2.z + h3.z;
            aw += h0.w + h1.w + h2.w + h3.w;
        }
        for (; j < end; j++) {
            int c0 = __ldg(&g_cols[j]);
            float4 h0 = *(const float4*)&g_h[c0 * 128 + lane * 4];
            ax += h0.x; ay += h0.y; az += h0.z; aw += h0.w;
        }
        float4 hs = *(const float4*)&g_h[node * 128 + lane * 4];
        float dn = __ldg(&g_dis[node]);
        ax = dn * (ax + hs.x) + bv.x;
        ay = dn * (ay + hs.y) + bv.y;
        az = dn * (az + hs.z) + bv.z;
        aw = dn * (aw + hs.w) + bv.w;
        *(float4*)&g_agg[node * 128 + lane * 4] = make_float4(ax, ay, az, aw);

        ls0 += ax; ls1 += ay; ls2 += az; ls3 += aw;
        lq0 += ax * ax; lq1 += ay * ay; lq2 += az * az; lq3 += aw * aw;
    }

    int sbase = layer * 2 * DD;
    red[wid][lane * 4 + 0] = ls0;
    red[wid][lane * 4 + 1] = ls1;
    red[wid][lane * 4 + 2] = ls2;
    red[wid][lane * 4 + 3] = ls3;
    __syncthreads();
    float tot = 0.f;
    #pragma unroll
    for (int w = 0; w < 8; w++) tot += red[w][tid];
    if (tid < 128) atomicAdd(&g_stats[sbase + tid], tot);
    __syncthreads();
    red[wid][lane * 4 + 0] = lq0;
    red[wid][lane * 4 + 1] = lq1;
    red[wid][lane * 4 + 2] = lq2;
    red[wid][lane * 4 + 3] = lq3;
    __syncthreads();
    tot = 0.f;
    #pragma unroll
    for (int w = 0; w < 8; w++) tot += red[w][tid];
    if (tid < 128) atomicAdd(&g_stats[sbase + DD + tid], tot);
}

// ---------------- Final elementwise: out = x2 + bn_2(agg2), no relu ----------------
__global__ __launch_bounds__(256) void elem_final_kernel(float* __restrict__ out,
                                                         const float* __restrict__ gamma,
                                                         const float* __restrict__ beta,
                                                         int n4, float invn) {
    __shared__ float sscale[DD];
    __shared__ float sshift[DD];
    int tid = threadIdx.x;
    if (tid < DD) {
        int base = 2 * 2 * DD;
        float s  = g_stats[base + tid];
        float sq = g_stats[base + DD + tid];
        float mean = s * invn;
        float var  = sq * invn - mean * mean;
        float istd = rsqrtf(var + 1e-5f);
        float sc = gamma[tid] * istd;
        sscale[tid] = sc;
        sshift[tid] = beta[tid] - mean * sc;
    }
    __syncthreads();

    int idx = blockIdx.x * blockDim.x + tid;
    if (idx >= n4) return;
    int c4 = idx & 31;
    float4 sc = ((const float4*)sscale)[c4];
    float4 sh = ((const float4*)sshift)[c4];
    float4 a  = ((const float4*)g_agg)[idx];
    float4 r  = ((const float4*)g_x)[idx];
    float4 y;
    y.x = a.x * sc.x + sh.x + r.x;
    y.y = a.y * sc.y + sh.y + r.y;
    y.z = a.z * sc.z + sh.z + r.z;
    y.w = a.w * sc.w + sh.w + r.w;
    ((float4*)out)[idx] = y;
}

// ---------------- launch ----------------
extern "C" void kernel_launch(void* const* d_in, const int* in_sizes, int n_in,
                              void* d_out, int out_size) {
    const float* x      = (const float*)d_in[0];
    const int*   ei     = (const int*)d_in[1];
    const float* Ws     = (const float*)d_in[2];
    const float* bs     = (const float*)d_in[3];
    const float* gammas = (const float*)d_in[4];
    const float* betas  = (const float*)d_in[5];

    int n = in_sizes[0] / DD;   // 50000
    int e = in_sizes[1] / 2;    // 800000
    const int* src = ei;
    const int* dst = ei + e;

    csr_build_kernel<<<CSR_GRID, 256>>>(src, dst, n, e);

    float invn = 1.0f / (float)n;
    int n4 = n * (DD / 4);
    int gemm_grid = (n + 63) / 64;
    int agg_grid = 1184;

    for (int l = 0; l < 3; l++) {
        int mode = (l > 0) ? 1 : 0;
        int residual = (l > 1) ? 1 : 0;
        const float* gprev = gammas + (l > 0 ? (l - 1) : 0) * DD;
        const float* bprev = betas + (l > 0 ? (l - 1) : 0) * DD;
        gemm_kernel<<<gemm_grid, 128>>>(x, Ws + l * DD * DD, gprev, bprev,
                                        n, mode, residual, l, invn);
        agg_kernel<<<agg_grid, 256>>>(bs + l * DD, n, l);
    }
    elem_final_kernel<<<(n4 + 255) / 256, 256>>>((float*)d_out, gammas + 2 * DD,
                                                 betas + 2 * DD, n4, invn);
}

// round 15
// speedup vs baseline: 1.2426x; 1.0659x over previous
#include <cuda_runtime.h>
#include <cuda_bf16.h>
#include <mma.h>
#include <math.h>

using namespace nvcuda;

#define NN 50000
#define EE 800000
#define DD 128
#define CSR_GRID 200

// ---------------- scratch (device globals; allocation-free rule) ----------------
__device__ int   g_deg[NN];
__device__ int   g_rowptr[NN + 1];
__device__ int   g_cursor[NN];
__device__ int   g_cols[EE];
__device__ float g_dis[NN];
__device__ int   g_bsum[256];
__device__ int   g_boff[256];
__device__ __align__(16) float g_h[NN * DD];
__device__ __align__(16) float g_agg[NN * DD];
__device__ __align__(16) float g_x[NN * DD];
__device__ float g_stats[3 * 2 * DD];   // per-layer: sum / sumsq
__device__ int   g_bar_count;
__device__ volatile int g_bar_phase;

// ---------------- grid barrier (sense-reversing, bounded spin) ----------------
__device__ __forceinline__ void grid_bar() {
    __syncthreads();
    if (threadIdx.x == 0) {
        int gen = g_bar_phase;
        __threadfence();
        if (atomicAdd(&g_bar_count, 1) == (int)gridDim.x - 1) {
            g_bar_count = 0;
            __threadfence();
            g_bar_phase = gen + 1;
        } else {
            for (int t = 0; t < (1 << 22) && g_bar_phase == gen; ++t) { }
        }
    }
    __syncthreads();
}

// ---------------- fused CSR build: zero + degree + scan + apply + fill ----------------
__global__ __launch_bounds__(256) void csr_build_kernel(const int* __restrict__ src,
                                                        const int* __restrict__ dst,
                                                        int n, int e) {
    __shared__ int wsum[8];
    int tid = threadIdx.x;
    int lane = tid & 31, wid = tid >> 5;
    int gtid = blockIdx.x * 256 + tid;
    int gsz = gridDim.x * 256;
    int nb = (n + 255) / 256;

    for (int i = gtid; i < n; i += gsz) g_deg[i] = 0;
    for (int i = gtid; i < 3 * 2 * DD; i += gsz) g_stats[i] = 0.0f;
    grid_bar();

    for (int i = gtid; i < e; i += gsz) atomicAdd(&g_deg[dst[i]], 1);
    grid_bar();

    for (int b = blockIdx.x; b < nb; b += gridDim.x) {
        __syncthreads();
        int i = b * 256 + tid;
        int v = (i < n) ? g_deg[i] : 0;
        int incl = v;
        #pragma unroll
        for (int off = 1; off < 32; off <<= 1) {
            int t = __shfl_up_sync(0xffffffffu, incl, off);
            if (lane >= off) incl += t;
        }
        if (lane == 31) wsum[wid] = incl;
        __syncthreads();
        if (wid == 0 && lane < 8) {
            int w = wsum[lane];
            int s = w;
            #pragma unroll
            for (int off = 1; off < 8; off <<= 1) {
                int t = __shfl_up_sync(0xffu, s, off);
                if (lane >= off) s += t;
            }
            wsum[lane] = s - w;
        }
        __syncthreads();
        int excl = incl - v + wsum[wid];
        if (i < n) g_rowptr[i] = excl;
        if (tid == 255) g_bsum[b] = excl + v;
    }
    grid_bar();

    if (blockIdx.x == 0) {
        int v = (tid < nb) ? g_bsum[tid] : 0;
        int incl = v;
        #pragma unroll
        for (int off = 1; off < 32; off <<= 1) {
            int t = __shfl_up_sync(0xffffffffu, incl, off);
            if (lane >= off) incl += t;
        }
        if (lane == 31) wsum[wid] = incl;
        __syncthreads();
        if (wid == 0 && lane < 8) {
            int w = wsum[lane];
            int s = w;
            #pragma unroll
            for (int off = 1; off < 8; off <<= 1) {
                int t = __shfl_up_sync(0xffu, s, off);
                if (lane >= off) s += t;
            }
            wsum[lane] = s - w;
        }
        __syncthreads();
        int excl = incl - v + wsum[wid];
        if (tid < nb) g_boff[tid] = excl;
        if (tid == nb - 1) g_rowptr[n] = excl + v;
    }
    grid_bar();

    for (int b = blockIdx.x; b < nb; b += gridDim.x) {
        int i = b * 256 + tid;
        if (i < n) {
            int excl = g_rowptr[i] + g_boff[b];
            g_rowptr[i] = excl;
            g_cursor[i] = excl;
            g_dis[i] = rsqrtf((float)g_deg[i] + 1.0f);
        }
    }
    grid_bar();

    for (int i = gtid; i < e; i += gsz) {
        int d = dst[i];
        int pos = atomicAdd(&g_cursor[d], 1);
        g_cols[pos] = src[i];
    }
}

// ---------------- WMMA GEMM: g_h = (dis .* X) @ W, split-bf16 x3 products ----------------
// block 128 threads (4 warps). M-tile 64 (warp w -> rows w*16..+15), N = 128 (8 n-tiles).
// K chunked by 32 (2 k-steps of 16). A stride 40 bf16, W stride 136 bf16 (padded, 16B rows).
// dis scaling folded into X conversion; accumulators stored directly to g_h.
// mode 0: X = Xext. mode 1: v = relu(bn_prev(agg)) (+ g_x if residual); g_x = v; X = v.
#define A_STRIDE 40
#define W_STRIDE 136

__global__ __launch_bounds__(128) void gemm_wmma_kernel(const float* __restrict__ Xext,
                                                        const float* __restrict__ W,
                                                        const float* __restrict__ gamma_prev,
                                                        const float* __restrict__ beta_prev,
                                                        int n, int mode, int residual,
                                                        int layer, float invn) {
    __shared__ __align__(16) __nv_bfloat16 As_hi[64 * A_STRIDE];
    __shared__ __align__(16) __nv_bfloat16 As_lo[64 * A_STRIDE];
    __shared__ __align__(16) __nv_bfloat16 Ws_hi[32 * W_STRIDE];
    __shared__ __align__(16) __nv_bfloat16 Ws_lo[32 * W_STRIDE];
    __shared__ float sscale[DD];
    __shared__ float sshift[DD];
    // scratch for partial-warp epilogue (aliases nothing; small)
    __shared__ __align__(16) float pscratch[16 * 20];

    int tid = threadIdx.x;
    int warp = tid >> 5;
    int m0 = blockIdx.x * 64;

    if (mode == 1) {
        if (tid < DD) {
            int base = (layer - 1) * 2 * DD;
            float s  = g_stats[base + tid];
            float sq = g_stats[base + DD + tid];
            float mean = s * invn;
            float var  = sq * invn - mean * mean;
            float istd = rsqrtf(var + 1e-5f);
            float sc = gamma_prev[tid] * istd;
            sscale[tid] = sc;
            sshift[tid] = beta_prev[tid] - mean * sc;
        }
        __syncthreads();
    }

    wmma::fragment<wmma::accumulator, 16, 16, 16, float> acc[8];
    #pragma unroll
    for (int nt = 0; nt < 8; nt++) wmma::fill_fragment(acc[nt], 0.0f);

    for (int kc = 0; kc < 128; kc += 32) {
        // ---- X chunk (64 rows x 32 k): fp32 -> dis-scaled hi/lo bf16 ----
        #pragma unroll
        for (int i = 0; i < 4; i++) {
            int f = tid + 128 * i;          // float4 index: 8 per row, 64 rows
            int r = f >> 3, k4 = f & 7;
            int row = m0 + r;
            float4 v = make_float4(0.f, 0.f, 0.f, 0.f);
            float dn = 0.0f;
            if (row < n) {
                dn = g_dis[row];
                int idx = row * 128 + kc + k4 * 4;
                if (mode == 0) {
                    v = *(const float4*)&Xext[idx];
                } else {
                    float4 a = *(const float4*)&g_agg[idx];
                    int c = kc + k4 * 4;
                    v.x = fmaxf(a.x * sscale[c + 0] + sshift[c + 0], 0.f);
                    v.y = fmaxf(a.y * sscale[c + 1] + sshift[c + 1], 0.f);
                    v.z = fmaxf(a.z * sscale[c + 2] + sshift[c + 2], 0.f);
                    v.w = fmaxf(a.w * sscale[c + 3] + sshift[c + 3], 0.f);
                    if (residual) {
                        float4 rr = *(const float4*)&g_x[idx];
                        v.x += rr.x; v.y += rr.y; v.z += rr.z; v.w += rr.w;
                    }
                    *(float4*)&g_x[idx] = v;
                }
            }
            // scale by dis, then split
            float sv[4] = { v.x * dn, v.y * dn, v.z * dn, v.w * dn };
            int base = r * A_STRIDE + k4 * 4;
            #pragma unroll
            for (int j = 0; j < 4; j++) {
                __nv_bfloat16 h = __float2bfloat16(sv[j]);
                __nv_bfloat16 l = __float2bfloat16(sv[j] - __bfloat162float(h));
                As_hi[base + j] = h;
                As_lo[base + j] = l;
            }
        }
        // ---- W chunk (32 k x 128 n): fp32 -> hi/lo bf16 ----
        #pragma unroll
        for (int i = 0; i < 8; i++) {
            int f = tid + 128 * i;          // float4 index: 32 per row, 32 rows
            int r = f >> 5, c4 = f & 31;
            float4 v = *(const float4*)&W[(kc + r) * 128 + c4 * 4];
            float sv[4] = { v.x, v.y, v.z, v.w };
            int base = r * W_STRIDE + c4 * 4;
            #pragma unroll
            for (int j = 0; j < 4; j++) {
                __nv_bfloat16 h = __float2bfloat16(sv[j]);
                __nv_bfloat16 l = __float2bfloat16(sv[j] - __bfloat162float(h));
                Ws_hi[base + j] = h;
                Ws_lo[base + j] = l;
            }
        }
        __syncthreads();

        // ---- MMA: 2 k-steps x 8 n-tiles x 3 products ----
        #pragma unroll
        for (int ks = 0; ks < 2; ks++) {
            wmma::fragment<wmma::matrix_a, 16, 16, 16, __nv_bfloat16, wmma::row_major> a_hi, a_lo;
            wmma::load_matrix_sync(a_hi, &As_hi[(warp * 16) * A_STRIDE + ks * 16], A_STRIDE);
            wmma::load_matrix_sync(a_lo, &As_lo[(warp * 16) * A_STRIDE + ks * 16], A_STRIDE);
            #pragma unroll
            for (int nt = 0; nt < 8; nt++) {
                wmma::fragment<wmma::matrix_b, 16, 16, 16, __nv_bfloat16, wmma::row_major> b_hi, b_lo;
                wmma::load_matrix_sync(b_hi, &Ws_hi[(ks * 16) * W_STRIDE + nt * 16], W_STRIDE);
                wmma::load_matrix_sync(b_lo, &Ws_lo[(ks * 16) * W_STRIDE + nt * 16], W_STRIDE);
                wmma::mma_sync(acc[nt], a_hi, b_hi, acc[nt]);
                wmma::mma_sync(acc[nt], a_lo, b_hi, acc[nt]);
                wmma::mma_sync(acc[nt], a_hi, b_lo, acc[nt]);
            }
        }
        __syncthreads();
    }

    // ---- epilogue: store fragments straight to g_h (dis already applied) ----
    int row_base = m0 + warp * 16;
    if (row_base + 16 <= n) {
        #pragma unroll
        for (int nt = 0; nt < 8; nt++) {
            wmma::store_matrix_sync(&g_h[row_base * 128 + nt * 16], acc[nt], 128,
                                    wmma::mem_row_major);
        }
    } else if (row_base < n) {
        // partial warp (only possible if n % 16 != 0): serialize warps through scratch
        for (int w = 0; w < 4; w++) {
            if (warp == w) {
                int nvalid = n - row_base;
                for (int nt = 0; nt < 8; nt++) {
                    wmma::store_matrix_sync(pscratch, acc[nt], 20, wmma::mem_row_major);
                    __syncwarp();
                    int lane = tid & 31;
                    for (int el = lane; el < nvalid * 16; el += 32) {
                        int rr = el >> 4, cc = el & 15;
                        g_h[(row_base + rr) * 128 + nt * 16 + cc] = pscratch[rr * 20 + cc];
                    }
                    __syncwarp();
                }
            }
            __syncthreads();
        }
    }
}

// ---------------- Aggregation (warp/node) + per-layer BN stat partials ----------------
__global__ __launch_bounds__(256) void agg_kernel(const float* __restrict__ bias, int n,
                                                  int layer) {
    __shared__ float red[8][256];
    int tid = threadIdx.x;
    int lane = tid & 31, wid = tid >> 5;
    float4 bv = *(const float4*)&bias[lane * 4];

    float ls0 = 0.f, ls1 = 0.f, ls2 = 0.f, ls3 = 0.f;
    float lq0 = 0.f, lq1 = 0.f, lq2 = 0.f, lq3 = 0.f;

    for (int node = blockIdx.x * 8 + wid; node < n; node += gridDim.x * 8) {
        int beg = __ldg(&g_rowptr[node]);
        int end = __ldg(&g_rowptr[node + 1]);
        float ax = 0.f, ay = 0.f, az = 0.f, aw = 0.f;
        int j = beg;
        for (; j + 3 < end; j += 4) {
            int c0 = __ldg(&g_cols[j]);
            int c1 = __ldg(&g_cols[j + 1]);
            int c2 = __ldg(&g_cols[j + 2]);
            int c3 = __ldg(&g_cols[j + 3]);
            float4 h0 = *(const float4*)&g_h[c0 * 128 + lane * 4];
            float4 h1 = *(const float4*)&g_h[c1 * 128 + lane * 4];
            float4 h2 = *(const float4*)&g_h[c2 * 128 + lane * 4];
            float4 h3 = *(const float4*)&g_h[c3 * 128 + lane * 4];
            ax += h0.x + h1.x + h2.x + h3.x;
            ay += h0.y + h1.y + h2.y + h3.y;
            az += h0.z + h1.z + h2.z + h3.z;
            aw += h0.w + h1.w + h2.w + h3.w;
        }
        for (; j < end; j++) {
            int c0 = __ldg(&g_cols[j]);
            float4 h0 = *(const float4*)&g_h[c0 * 128 + lane * 4];
            ax += h0.x; ay += h0.y; az += h0.z; aw += h0.w;
        }
        float4 hs = *(const float4*)&g_h[node * 128 + lane * 4];
        float dn = __ldg(&g_dis[node]);
        ax = dn * (ax + hs.x) + bv.x;
        ay = dn * (ay + hs.y) + bv.y;
        az = dn * (az + hs.z) + bv.z;
        aw = dn * (aw + hs.w) + bv.w;
        *(float4*)&g_agg[node * 128 + lane * 4] = make_float4(ax, ay, az, aw);

        ls0 += ax; ls1 += ay; ls2 += az; ls3 += aw;
        lq0 += ax * ax; lq1 += ay * ay; lq2 += az * az; lq3 += aw * aw;
    }

    int sbase = layer * 2 * DD;
    red[wid][lane * 4 + 0] = ls0;
    red[wid][lane * 4 + 1] = ls1;
    red[wid][lane * 4 + 2] = ls2;
    red[wid][lane * 4 + 3] = ls3;
    __syncthreads();
    float tot = 0.f;
    #pragma unroll
    for (int w = 0; w < 8; w++) tot += red[w][tid];
    if (tid < 128) atomicAdd(&g_stats[sbase + tid], tot);
    __syncthreads();
    red[wid][lane * 4 + 0] = lq0;
    red[wid][lane * 4 + 1] = lq1;
    red[wid][lane * 4 + 2] = lq2;
    red[wid][lane * 4 + 3] = lq3;
    __syncthreads();
    tot = 0.f;
    #pragma unroll
    for (int w = 0; w < 8; w++) tot += red[w][tid];
    if (tid < 128) atomicAdd(&g_stats[sbase + DD + tid], tot);
}

// ---------------- Final elementwise: out = x2 + bn_2(agg2), no relu ----------------
__global__ __launch_bounds__(256) void elem_final_kernel(float* __restrict__ out,
                                                         const float* __restrict__ gamma,
                                                         const float* __restrict__ beta,
                                                         int n4, float invn) {
    __shared__ float sscale[DD];
    __shared__ float sshift[DD];
    int tid = threadIdx.x;
    if (tid < DD) {
        int base = 2 * 2 * DD;
        float s  = g_stats[base + tid];
        float sq = g_stats[base + DD + tid];
        float mean = s * invn;
        float var  = sq * invn - mean * mean;
        float istd = rsqrtf(var + 1e-5f);
        float sc = gamma[tid] * istd;
        sscale[tid] = sc;
        sshift[tid] = beta[tid] - mean * sc;
    }
    __syncthreads();

    int idx = blockIdx.x * blockDim.x + tid;
    if (idx >= n4) return;
    int c4 = idx & 31;
    float4 sc = ((const float4*)sscale)[c4];
    float4 sh = ((const float4*)sshift)[c4];
    float4 a  = ((const float4*)g_agg)[idx];
    float4 r  = ((const float4*)g_x)[idx];
    float4 y;
    y.x = a.x * sc.x + sh.x + r.x;
    y.y = a.y * sc.y + sh.y + r.y;
    y.z = a.z * sc.z + sh.z + r.z;
    y.w = a.w * sc.w + sh.w + r.w;
    ((float4*)out)[idx] = y;
}

// ---------------- launch ----------------
extern "C" void kernel_launch(void* const* d_in, const int* in_sizes, int n_in,
                              void* d_out, int out_size) {
    const float* x      = (const float*)d_in[0];
    const int*   ei     = (const int*)d_in[1];
    const float* Ws     = (const float*)d_in[2];
    const float* bs     = (const float*)d_in[3];
    const float* gammas = (const float*)d_in[4];
    const float* betas  = (const float*)d_in[5];

    int n = in_sizes[0] / DD;   // 50000
    int e = in_sizes[1] / 2;    // 800000
    const int* src = ei;
    const int* dst = ei + e;

    csr_build_kernel<<<CSR_GRID, 256>>>(src, dst, n, e);

    float invn = 1.0f / (float)n;
    int n4 = n * (DD / 4);
    int gemm_grid = (n + 63) / 64;
    int agg_grid = 1184;

    for (int l = 0; l < 3; l++) {
        int mode = (l > 0) ? 1 : 0;
        int residual = (l > 1) ? 1 : 0;
        const float* gprev = gammas + (l > 0 ? (l - 1) : 0) * DD;
        const float* bprev = betas + (l > 0 ? (l - 1) : 0) * DD;
        gemm_wmma_kernel<<<gemm_grid, 128>>>(x, Ws + l * DD * DD, gprev, bprev,
                                             n, mode, residual, l, invn);
        agg_kernel<<<agg_grid, 256>>>(bs + l * DD, n, l);
    }
    elem_final_kernel<<<(n4 + 255) / 256, 256>>>((float*)d_out, gammas + 2 * DD,
                                                 betas + 2 * DD, n4, invn);
}